// round 2
// baseline (speedup 1.0000x reference)
#include <cuda_runtime.h>

#define CA_EPS 1e-8f
#define CA_K 512
#define CA_FF 16          // F*F = 16 elements per channel
#define CA_HALF 8192      // K * FF: size of x-flat per batch / offset of xc half in W row
#define CA_FEAT 16384     // 2 * K * FF: W row length

// One block per batch element, one thread per channel.
__global__ __launch_bounds__(512, 1)
void resnet18ca_kernel(const float* __restrict__ x,
                       const float* __restrict__ W,
                       const float* __restrict__ bias,
                       float* __restrict__ out) {
    const int b = blockIdx.x;       // batch index (0..1)
    const int k = threadIdx.x;      // channel index (0..511)
    const int lane = k & 31;
    const int warp = k >> 5;

    __shared__ float s_red[16];     // warp partials (max, then sums)
    __shared__ float s_bcast;       // broadcast max
    __shared__ float s_D[CA_K];     // lehmer_den per channel
    __shared__ float s_p0[16];
    __shared__ float s_p1[16];

    // ---- load this channel's 16 x values (contiguous: layout [b,k,f,f]) ----
    const float4* xv4 = reinterpret_cast<const float4*>(x + (size_t)b * CA_HALF + (size_t)k * CA_FF);
    float4 q0 = xv4[0], q1 = xv4[1], q2 = xv4[2], q3 = xv4[3];
    float xv[16] = {q0.x, q0.y, q0.z, q0.w,
                    q1.x, q1.y, q1.z, q1.w,
                    q2.x, q2.y, q2.z, q2.w,
                    q3.x, q3.y, q3.z, q3.w};

    // ---- phase 1: global max over this batch element ----
    float m = xv[0];
    #pragma unroll
    for (int i = 1; i < 16; ++i) m = fmaxf(m, xv[i]);
    #pragma unroll
    for (int off = 16; off > 0; off >>= 1)
        m = fmaxf(m, __shfl_xor_sync(0xFFFFFFFFu, m, off));
    if (lane == 0) s_red[warp] = m;
    __syncthreads();
    if (warp == 0) {
        float mm = s_red[lane & 15];
        #pragma unroll
        for (int off = 8; off > 0; off >>= 1)
            mm = fmaxf(mm, __shfl_xor_sync(0xFFFFFFFFu, mm, off));
        if (lane == 0) s_bcast = mm;
    }
    __syncthreads();
    const float maxf = s_bcast;
    const float inv = 1.0f / (maxf + CA_EPS);

    // ---- phase 2: lehmer_den D[k] from the 16 normalized values ----
    float s1 = 0.0f, s2 = 0.0f;
    #pragma unroll
    for (int i = 0; i < 16; ++i) {
        float xa = xv[i] * inv + CA_EPS;   // |x_norm| + EPS (x >= 0)
        s1 += xa;
        s2 += xa * xa;
    }
    const float D = (s2 + CA_EPS) / (s1 + CA_EPS) + CA_EPS;
    s_D[k] = D;
    __syncthreads();

    // ---- phase 3: pairwise comparison -> mul_factor[k] ----
    // bool[m,n] = (cm[m,n] > cm[n,m]) == (D[m] > D[n]); factor = relu(wins - losses)
    int wins = 0, losses = 0;
    #pragma unroll 8
    for (int n = 0; n < CA_K; ++n) {
        float dn = s_D[n];                 // broadcast read, conflict-free
        wins   += (D > dn);
        losses += (dn > D);
    }
    const float fac = fmaxf((float)(wins - losses), 0.0f);

    // ---- phase 4: logits = bias + x . (W_x + fac * W_xc) for both classes ----
    const float4* w0a = reinterpret_cast<const float4*>(W + (size_t)0 * CA_FEAT + (size_t)k * CA_FF);
    const float4* w0b = reinterpret_cast<const float4*>(W + (size_t)0 * CA_FEAT + CA_HALF + (size_t)k * CA_FF);
    const float4* w1a = reinterpret_cast<const float4*>(W + (size_t)1 * CA_FEAT + (size_t)k * CA_FF);
    const float4* w1b = reinterpret_cast<const float4*>(W + (size_t)1 * CA_FEAT + CA_HALF + (size_t)k * CA_FF);

    float p0 = 0.0f, p1 = 0.0f;
    #pragma unroll
    for (int v = 0; v < 4; ++v) {
        float4 a0 = w0a[v], b0 = w0b[v];
        float4 a1 = w1a[v], b1 = w1b[v];
        const float* xp = &xv[v * 4];
        p0 += xp[0] * fmaf(fac, b0.x, a0.x);
        p0 += xp[1] * fmaf(fac, b0.y, a0.y);
        p0 += xp[2] * fmaf(fac, b0.z, a0.z);
        p0 += xp[3] * fmaf(fac, b0.w, a0.w);
        p1 += xp[0] * fmaf(fac, b1.x, a1.x);
        p1 += xp[1] * fmaf(fac, b1.y, a1.y);
        p1 += xp[2] * fmaf(fac, b1.z, a1.z);
        p1 += xp[3] * fmaf(fac, b1.w, a1.w);
    }

    // block-wide sum of p0, p1
    #pragma unroll
    for (int off = 16; off > 0; off >>= 1) {
        p0 += __shfl_xor_sync(0xFFFFFFFFu, p0, off);
        p1 += __shfl_xor_sync(0xFFFFFFFFu, p1, off);
    }
    if (lane == 0) { s_p0[warp] = p0; s_p1[warp] = p1; }
    __syncthreads();
    if (warp == 0) {
        float t0 = s_p0[lane & 15];
        float t1 = s_p1[lane & 15];
        #pragma unroll
        for (int off = 8; off > 0; off >>= 1) {
            t0 += __shfl_xor_sync(0xFFFFFFFFu, t0, off);
            t1 += __shfl_xor_sync(0xFFFFFFFFu, t1, off);
        }
        if (lane == 0) {
            out[b * 2 + 0] = bias[0] + t0;
            out[b * 2 + 1] = bias[1] + t1;
        }
    }
}

extern "C" void kernel_launch(void* const* d_in, const int* in_sizes, int n_in,
                              void* d_out, int out_size) {
    const float* x    = (const float*)d_in[0];   // [2, 512, 4, 4]
    const float* W    = (const float*)d_in[1];   // [2, 16384]
    const float* bias = (const float*)d_in[2];   // [2]
    float* out = (float*)d_out;                  // [2, 2]
    resnet18ca_kernel<<<2, 512>>>(x, W, bias, out);
}

// round 3
// speedup vs baseline: 2.1183x; 2.1183x over previous
#include <cuda_runtime.h>

#define CA_EPS  1e-8f
#define CA_K    512
#define CA_FF   16          // F*F
#define CA_HALF 8192        // K*FF : x-flat size per batch / xc-half offset in W row
#define CA_FEAT 16384       // 2*K*FF : W row length
#define SLICE   16          // channels handled per CTA
#define NT      256

// out[b*2+c] = bias[c]
__global__ void ca_init(const float* __restrict__ bias, float* __restrict__ out) {
    int i = threadIdx.x;
    if (i < 4) out[i] = bias[i & 1];
}

// grid = 64 (32 CTAs per batch), block = 256.
// Every CTA redundantly computes max + all 512 lehmer_den values (bitwise
// identical across CTAs), then handles comparisons + matvec for its
// 16-channel slice, accumulating into out via atomicAdd.
__global__ __launch_bounds__(NT, 1)
void ca_main(const float* __restrict__ x, const float* __restrict__ W,
             float* __restrict__ out) {
    const int b   = blockIdx.x >> 5;            // batch (0..1)
    const int c0  = (blockIdx.x & 31) * SLICE;  // slice start channel
    const int tid = threadIdx.x;
    const int lane = tid & 31, warp = tid >> 5;

    __shared__ float s_red[8];
    __shared__ float s_max;
    __shared__ float s_D[CA_K];
    __shared__ int   s_wl[16][17];              // [portion][slice-channel], padded
    __shared__ float s_fac[SLICE];
    __shared__ float s_wsum[4];

    // ---- prefetch matvec operands (threads 0..127) -------------------------
    // unit: class = tid>>6, u = tid&63 -> ch_l = u>>2 (0..15), v = u&3 (0..3)
    float4 wa = make_float4(0.f, 0.f, 0.f, 0.f);
    float4 wb = wa, xu = wa;
    int ch_l = 0;
    if (tid < 128) {
        const int cls = tid >> 6;
        const int u   = tid & 63;
        ch_l = u >> 2;
        const int v = u & 3;
        const float* wbase = W + (size_t)cls * CA_FEAT + (size_t)(c0 + ch_l) * CA_FF + v * 4;
        wa = *reinterpret_cast<const float4*>(wbase);
        wb = *reinterpret_cast<const float4*>(wbase + CA_HALF);
        xu = *reinterpret_cast<const float4*>(x + (size_t)b * CA_HALF + (size_t)(c0 + ch_l) * CA_FF + v * 4);
    }

    // ---- load own two channels (2*tid, 2*tid+1): 8 contiguous float4 ------
    const float4* xp = reinterpret_cast<const float4*>(x + (size_t)b * CA_HALF) + (size_t)tid * 8;
    float4 a[8];
    #pragma unroll
    for (int i = 0; i < 8; ++i) a[i] = xp[i];

    // ---- phase 1: per-batch global max -------------------------------------
    float m = a[0].x;
    #pragma unroll
    for (int i = 0; i < 8; ++i) {
        m = fmaxf(m, fmaxf(fmaxf(a[i].x, a[i].y), fmaxf(a[i].z, a[i].w)));
    }
    #pragma unroll
    for (int off = 16; off > 0; off >>= 1)
        m = fmaxf(m, __shfl_xor_sync(0xFFFFFFFFu, m, off));
    if (lane == 0) s_red[warp] = m;
    __syncthreads();
    if (warp == 0) {
        float mm = s_red[lane & 7];
        #pragma unroll
        for (int off = 4; off > 0; off >>= 1)
            mm = fmaxf(mm, __shfl_xor_sync(0xFFFFFFFFu, mm, off));
        if (lane == 0) s_max = mm;
    }
    __syncthreads();
    const float inv = 1.0f / (s_max + CA_EPS);

    // ---- phase 2: lehmer_den D for the two owned channels ------------------
    {
        float s1 = 0.f, s2 = 0.f;
        #pragma unroll
        for (int i = 0; i < 4; ++i) {
            float t;
            t = a[i].x * inv + CA_EPS; s1 += t; s2 += t * t;
            t = a[i].y * inv + CA_EPS; s1 += t; s2 += t * t;
            t = a[i].z * inv + CA_EPS; s1 += t; s2 += t * t;
            t = a[i].w * inv + CA_EPS; s1 += t; s2 += t * t;
        }
        s_D[2 * tid] = (s2 + CA_EPS) / (s1 + CA_EPS) + CA_EPS;
    }
    {
        float s1 = 0.f, s2 = 0.f;
        #pragma unroll
        for (int i = 4; i < 8; ++i) {
            float t;
            t = a[i].x * inv + CA_EPS; s1 += t; s2 += t * t;
            t = a[i].y * inv + CA_EPS; s1 += t; s2 += t * t;
            t = a[i].z * inv + CA_EPS; s1 += t; s2 += t * t;
            t = a[i].w * inv + CA_EPS; s1 += t; s2 += t * t;
        }
        s_D[2 * tid + 1] = (s2 + CA_EPS) / (s1 + CA_EPS) + CA_EPS;
    }
    __syncthreads();

    // ---- phase 3: pairwise compares for the slice --------------------------
    // bool[m,n] decision reduces to D[m] vs D[n]; fac = relu(wins - losses).
    {
        const int sc = tid & 15;       // slice channel
        const int p  = tid >> 4;       // portion of the 512 n-values
        const float Dk = s_D[c0 + sc];
        const float* dn = s_D + p * 32;
        int wl = 0;
        #pragma unroll
        for (int i = 0; i < 32; ++i) {      // broadcast LDS (lanes share p)
            float d = dn[i];
            wl += (Dk > d) - (d > Dk);
        }
        s_wl[p][sc] = wl;
    }
    __syncthreads();
    if (tid < 16) {
        int s = 0;
        #pragma unroll
        for (int p2 = 0; p2 < 16; ++p2) s += s_wl[p2][tid];
        s_fac[tid] = fmaxf((float)s, 0.0f);
    }
    __syncthreads();

    // ---- phase 4: slice matvec partial -> atomicAdd ------------------------
    float part = 0.0f;
    if (tid < 128) {
        const float f = s_fac[ch_l];
        part  = xu.x * fmaf(f, wb.x, wa.x);
        part += xu.y * fmaf(f, wb.y, wa.y);
        part += xu.z * fmaf(f, wb.z, wa.z);
        part += xu.w * fmaf(f, wb.w, wa.w);
    }
    #pragma unroll
    for (int off = 16; off > 0; off >>= 1)
        part += __shfl_xor_sync(0xFFFFFFFFu, part, off);
    if (lane == 0 && warp < 4) s_wsum[warp] = part;
    __syncthreads();
    if (tid == 0) atomicAdd(out + b * 2 + 0, s_wsum[0] + s_wsum[1]);
    if (tid == 1) atomicAdd(out + b * 2 + 1, s_wsum[2] + s_wsum[3]);
}

extern "C" void kernel_launch(void* const* d_in, const int* in_sizes, int n_in,
                              void* d_out, int out_size) {
    const float* x    = (const float*)d_in[0];   // [2, 512, 4, 4]
    const float* W    = (const float*)d_in[1];   // [2, 16384]
    const float* bias = (const float*)d_in[2];   // [2]
    float* out = (float*)d_out;                  // [2, 2]
    ca_init<<<1, 32>>>(bias, out);
    ca_main<<<64, NT>>>(x, W, out);
}

// round 4
// speedup vs baseline: 2.1808x; 1.0295x over previous
#include <cuda_runtime.h>

#define CA_EPS  1e-8f
#define CA_K    512
#define CA_FF   16          // F*F
#define CA_HALF 8192        // K*FF : x-flat per batch / xc-half offset in W row
#define CA_FEAT 16384       // 2*K*FF : W row length
#define SLICE   16
#define NT      512
#define GRID    64

__device__ float    g_accum[4];   // zero-init; returned to zero every call
__device__ unsigned g_count;      // zero-init; returned to zero every call

// grid = 64 (32 slice-CTAs per batch), block = 512 (one thread per channel).
__global__ __launch_bounds__(NT, 1)
void ca_fused(const float* __restrict__ x, const float* __restrict__ W,
              const float* __restrict__ bias, float* __restrict__ out) {
    const int b    = blockIdx.x >> 5;            // batch (0..1)
    const int c0   = (blockIdx.x & 31) * SLICE;  // slice start channel
    const int tid  = threadIdx.x;
    const int lane = tid & 31, warp = tid >> 5;

    __shared__ float s_red[16];
    __shared__ float s_D[CA_K];
    __shared__ int   s_wl[32][17];               // [portion][slice-channel], padded
    __shared__ float s_fac[SLICE];

    // ---- prefetch matvec operands (threads 0..127) -------------------------
    float4 wa = make_float4(0.f, 0.f, 0.f, 0.f);
    float4 wb = wa, xu = wa;
    int ch_l = 0;
    if (tid < 128) {
        const int cls = tid >> 6;                // warp0,1 -> class0; warp2,3 -> class1
        const int u   = tid & 63;
        ch_l = u >> 2;
        const int v = u & 3;
        const float* wbase = W + (size_t)cls * CA_FEAT + (size_t)(c0 + ch_l) * CA_FF + v * 4;
        wa = *reinterpret_cast<const float4*>(wbase);
        wb = *reinterpret_cast<const float4*>(wbase + CA_HALF);
        xu = *reinterpret_cast<const float4*>(x + (size_t)b * CA_HALF + (size_t)(c0 + ch_l) * CA_FF + v * 4);
    }

    // ---- load own channel (k = tid): 4 contiguous float4 -------------------
    const float4* xp = reinterpret_cast<const float4*>(x + (size_t)b * CA_HALF) + (size_t)tid * 4;
    float4 a0 = xp[0], a1 = xp[1], a2 = xp[2], a3 = xp[3];

    // ---- phase 1: per-batch global max -------------------------------------
    float m = fmaxf(fmaxf(fmaxf(a0.x, a0.y), fmaxf(a0.z, a0.w)),
                    fmaxf(fmaxf(a1.x, a1.y), fmaxf(a1.z, a1.w)));
    m = fmaxf(m, fmaxf(fmaxf(fmaxf(a2.x, a2.y), fmaxf(a2.z, a2.w)),
                       fmaxf(fmaxf(a3.x, a3.y), fmaxf(a3.z, a3.w))));
    #pragma unroll
    for (int off = 16; off > 0; off >>= 1)
        m = fmaxf(m, __shfl_xor_sync(0xFFFFFFFFu, m, off));
    if (lane == 0) s_red[warp] = m;
    __syncthreads();
    float mm = s_red[0];
    #pragma unroll
    for (int i = 1; i < 16; ++i) mm = fmaxf(mm, s_red[i]);
    const float inv = 1.0f / (mm + CA_EPS);

    // ---- phase 2: lehmer_den D for the own channel -------------------------
    {
        float s1 = 0.f, s2 = 0.f, t;
        t = a0.x * inv + CA_EPS; s1 += t; s2 += t * t;
        t = a0.y * inv + CA_EPS; s1 += t; s2 += t * t;
        t = a0.z * inv + CA_EPS; s1 += t; s2 += t * t;
        t = a0.w * inv + CA_EPS; s1 += t; s2 += t * t;
        t = a1.x * inv + CA_EPS; s1 += t; s2 += t * t;
        t = a1.y * inv + CA_EPS; s1 += t; s2 += t * t;
        t = a1.z * inv + CA_EPS; s1 += t; s2 += t * t;
        t = a1.w * inv + CA_EPS; s1 += t; s2 += t * t;
        t = a2.x * inv + CA_EPS; s1 += t; s2 += t * t;
        t = a2.y * inv + CA_EPS; s1 += t; s2 += t * t;
        t = a2.z * inv + CA_EPS; s1 += t; s2 += t * t;
        t = a2.w * inv + CA_EPS; s1 += t; s2 += t * t;
        t = a3.x * inv + CA_EPS; s1 += t; s2 += t * t;
        t = a3.y * inv + CA_EPS; s1 += t; s2 += t * t;
        t = a3.z * inv + CA_EPS; s1 += t; s2 += t * t;
        t = a3.w * inv + CA_EPS; s1 += t; s2 += t * t;
        s_D[tid] = (s2 + CA_EPS) / (s1 + CA_EPS) + CA_EPS;
    }
    __syncthreads();

    // ---- phase 3: pairwise compares for the slice --------------------------
    // bool[m,n] reduces to sign(D[m] - D[n]); fac = relu(wins - losses).
    {
        const int sc = tid & 15;        // slice channel
        const int p  = tid >> 4;        // portion (0..31) of the 512 n-values
        const float Dk = s_D[c0 + sc];
        const float* dn = s_D + p * 16;
        int wl = 0;
        #pragma unroll
        for (int i = 0; i < 16; ++i) {  // broadcast LDS within warp
            float d = dn[i];
            wl += (Dk > d) - (d > Dk);
        }
        s_wl[p][sc] = wl;
    }
    __syncthreads();
    if (tid < 16) {
        int s = 0;
        #pragma unroll
        for (int p2 = 0; p2 < 32; ++p2) s += s_wl[p2][tid];
        s_fac[tid] = fmaxf((float)s, 0.0f);
    }
    __syncthreads();

    // ---- phase 4: slice matvec partial -> global RED -----------------------
    if (warp < 4) {
        float part = 0.0f;
        if (tid < 128) {
            const float f = s_fac[ch_l];
            part  = xu.x * fmaf(f, wb.x, wa.x);
            part += xu.y * fmaf(f, wb.y, wa.y);
            part += xu.z * fmaf(f, wb.z, wa.z);
            part += xu.w * fmaf(f, wb.w, wa.w);
        }
        #pragma unroll
        for (int off = 16; off > 0; off >>= 1)
            part += __shfl_xor_sync(0xFFFFFFFFu, part, off);
        if (lane == 0) atomicAdd(&g_accum[b * 2 + (warp >> 1)], part);
    }
    __syncthreads();

    // ---- last-CTA finalize (also resets scratch to zero for next call) -----
    if (tid == 0) {
        __threadfence();
        unsigned ticket = atomicAdd(&g_count, 1u);
        if (ticket == GRID - 1) {
            float r0 = atomicExch(&g_accum[0], 0.0f);
            float r1 = atomicExch(&g_accum[1], 0.0f);
            float r2 = atomicExch(&g_accum[2], 0.0f);
            float r3 = atomicExch(&g_accum[3], 0.0f);
            float b0 = bias[0], b1 = bias[1];
            out[0] = b0 + r0;
            out[1] = b1 + r1;
            out[2] = b0 + r2;
            out[3] = b1 + r3;
            atomicExch(&g_count, 0u);
        }
    }
}

extern "C" void kernel_launch(void* const* d_in, const int* in_sizes, int n_in,
                              void* d_out, int out_size) {
    const float* x    = (const float*)d_in[0];   // [2, 512, 4, 4]
    const float* W    = (const float*)d_in[1];   // [2, 16384]
    const float* bias = (const float*)d_in[2];   // [2]
    float* out = (float*)d_out;                  // [2, 2]
    ca_fused<<<GRID, NT>>>(x, W, bias, out);
}